// round 1
// baseline (speedup 1.0000x reference)
#include <cuda_runtime.h>
#include <cstdint>

// Problem constants (hardcoded; inputs are fixed-shape)
#define BB    8192
#define TT    100
#define INF   16
#define HH    128
#define G4    512
#define TGTN  60

#define NT    512     // threads per CTA
#define BR    64      // batch rows per CTA
#define HPAD  68      // row-padded state stride (floats), 16B-aligned, conflict-free
#define WPAD  516     // gate-padded weight-chunk stride (floats)

// Shared memory layout (float offsets)
#define OFF_H0   0
#define OFF_H1   (128*HPAD)            // 8704
#define OFF_C0   (2*128*HPAD)
#define OFF_C1   (3*128*HPAD)
#define OFF_WIH0 (4*128*HPAD)          // 34816  -- transposed ih0 weights [16][516] (enc) / [2][516] (dec)
#define OFF_WBUF (OFF_WIH0 + 16*WPAD)  // 43072  -- streamed weight chunk [16][516]
#define OFF_XS   (OFF_WBUF + 16*WPAD)  // 51328  -- x_t / decoder input, [16][68]
#define OFF_BIAS (OFF_XS + 16*HPAD)    // 52416  -- 4 layers x 512 combined biases
#define OFF_FC   (OFF_BIAS + 4*512)    // 54464  -- fcW [2][128]
#define OFF_FCB  (OFF_FC + 256)        // 54720
#define SMEM_FLOATS (OFF_FCB + 2)      // 54722
#define SMEM_BYTES  (SMEM_FLOATS * 4)  // 218888 bytes

typedef unsigned long long u64;

// ---- packed f32x2 helpers (Blackwell 2x fp32 throughput) ----
__device__ __forceinline__ u64 pk2(float x) {
    u64 r;
    asm("mov.b64 %0, {%1, %1};" : "=l"(r) : "f"(x));
    return r;
}
__device__ __forceinline__ u64 f2fma(u64 a, u64 b, u64 c) {
    u64 d;
    asm("fma.rn.f32x2 %0, %1, %2, %3;" : "=l"(d) : "l"(a), "l"(b), "l"(c));
    return d;
}
__device__ __forceinline__ float2 up2(u64 v) {
    float2 f;
    asm("mov.b64 {%0, %1}, %2;" : "=f"(f.x), "=f"(f.y) : "l"(v));
    return f;
}

// ---- activations (fast exp, full-precision-safe forms) ----
__device__ __forceinline__ float sigm(float x) {
    // 1/(1+e^{-x}); __expf overflow -> inf -> result 0 (correct)
    return __fdividef(1.0f, 1.0f + __expf(-x));
}
__device__ __forceinline__ float tanh_(float x) {
    float a = fabsf(x);
    float e = __expf(-2.0f * a);           // e in (0,1], no overflow
    float t = __fdividef(1.0f - e, 1.0f + e);
    return copysignf(t, x);
}

// ---- inner GEMM: accumulate KS k-slices from wbuf-style [KS][WPAD] weights
//      and hb-style [k][HPAD] activations (hb already offset by rowbase) ----
template<int KS>
__device__ __forceinline__ void accum(u64 acc[4][8],
                                      const float* __restrict__ wb,
                                      const float* __restrict__ hb,
                                      int j)
{
#pragma unroll
    for (int k = 0; k < KS; k++) {
        const float* w = wb + k * WPAD + j;
        u64 b0 = pk2(w[0]);
        u64 b1 = pk2(w[128]);
        u64 b2 = pk2(w[256]);
        u64 b3 = pk2(w[384]);
        const ulonglong2* hp = (const ulonglong2*)(hb + k * HPAD);
        ulonglong2 q0 = hp[0], q1 = hp[1], q2 = hp[2], q3 = hp[3];
        u64 a[8] = {q0.x, q0.y, q1.x, q1.y, q2.x, q2.y, q3.x, q3.y};
#pragma unroll
        for (int p = 0; p < 8; p++) {
            acc[0][p] = f2fma(a[p], b0, acc[0][p]);
            acc[1][p] = f2fma(a[p], b1, acc[1][p]);
            acc[2][p] = f2fma(a[p], b2, acc[2][p]);
            acc[3][p] = f2fma(a[p], b3, acc[3][p]);
        }
    }
}

// ---- K=128 GEMM from global weights W [512][128], streamed in 8 chunks of 16 ----
__device__ __forceinline__ void gemm128(u64 acc[4][8],
                                        const float* __restrict__ W,
                                        const float* __restrict__ hsrc,  // sm + OFF_Hx + rowbase
                                        float* __restrict__ sm,
                                        int tid, int j)
{
    float* wb = sm + OFF_WBUF;
#pragma unroll 1
    for (int kc = 0; kc < 8; kc++) {
        __syncthreads();   // previous wbuf consumers done
        // copy chunk: thread tid owns gate-row tid, 16 k's
        {
            const float4* src = (const float4*)(W + (size_t)tid * 128 + kc * 16);
            float v[16];
            *(float4*)(v + 0)  = src[0];
            *(float4*)(v + 4)  = src[1];
            *(float4*)(v + 8)  = src[2];
            *(float4*)(v + 12) = src[3];
            float* d = wb + tid;
#pragma unroll
            for (int k = 0; k < 16; k++) d[k * WPAD] = v[k];
        }
        __syncthreads();   // chunk visible
        accum<16>(acc, wb, hsrc + kc * 16 * HPAD, j);
    }
}

__device__ __forceinline__ void init_acc(u64 acc[4][8], const float* __restrict__ bias, int j)
{
#pragma unroll
    for (int g = 0; g < 4; g++) {
        u64 b = pk2(bias[g * 128 + j]);
#pragma unroll
        for (int p = 0; p < 8; p++) acc[g][p] = b;
    }
}

// ---- LSTM pointwise epilogue: updates c (shared) and h (shared) for this
//      thread's unit j, rows rowbase..rowbase+15 ----
__device__ __forceinline__ void epilogue(u64 acc[4][8],
                                         float* __restrict__ cs,
                                         float* __restrict__ hs,
                                         int j, int rowbase)
{
    float* cp = cs + j * HPAD + rowbase;
    float* hp = hs + j * HPAD + rowbase;
#pragma unroll
    for (int p = 0; p < 8; p++) {
        float2 gi = up2(acc[0][p]);
        float2 gf = up2(acc[1][p]);
        float2 gg = up2(acc[2][p]);
        float2 go = up2(acc[3][p]);
        int r = 2 * p;
        float c0 = cp[r], c1 = cp[r + 1];
        float cn0 = sigm(gf.x) * c0 + sigm(gi.x) * tanh_(gg.x);
        float cn1 = sigm(gf.y) * c1 + sigm(gi.y) * tanh_(gg.y);
        cp[r]     = cn0;
        cp[r + 1] = cn1;
        hp[r]     = sigm(go.x) * tanh_(cn0);
        hp[r + 1] = sigm(go.y) * tanh_(cn1);
    }
}

__global__ void __launch_bounds__(NT, 1)
lstm_traj_kernel(const float* __restrict__ x,
                 const float* __restrict__ eWih0, const float* __restrict__ eWhh0,
                 const float* __restrict__ ebih0, const float* __restrict__ ebhh0,
                 const float* __restrict__ eWih1, const float* __restrict__ eWhh1,
                 const float* __restrict__ ebih1, const float* __restrict__ ebhh1,
                 const float* __restrict__ dWih0, const float* __restrict__ dWhh0,
                 const float* __restrict__ dbih0, const float* __restrict__ dbhh0,
                 const float* __restrict__ dWih1, const float* __restrict__ dWhh1,
                 const float* __restrict__ dbih1, const float* __restrict__ dbhh1,
                 const float* __restrict__ fcW,  const float* __restrict__ fcb,
                 float* __restrict__ out)
{
    extern __shared__ float sm[];
    const int tid = threadIdx.x;
    const int j = tid >> 2;              // hidden unit 0..127
    const int rowbase = (tid & 3) * 16;  // 16-row block 0/16/32/48
    const int gr0 = blockIdx.x * BR;     // first global batch row of this CTA

    // ---------- init: zero states, stage biases / fc / transposed eWih0 ----------
    for (int i = tid; i < 4 * 128 * HPAD; i += NT) sm[i] = 0.0f;
    sm[OFF_BIAS + tid]        = ebih0[tid] + ebhh0[tid];
    sm[OFF_BIAS + 512 + tid]  = ebih1[tid] + ebhh1[tid];
    sm[OFF_BIAS + 1024 + tid] = dbih0[tid] + dbhh0[tid];
    sm[OFF_BIAS + 1536 + tid] = dbih1[tid] + dbhh1[tid];
    if (tid < 256) sm[OFF_FC + tid] = fcW[tid];
    if (tid < 2)   sm[OFF_FCB + tid] = fcb[tid];
    {   // eWih0 [512][16] -> transposed [16][516]
        const float4* s = (const float4*)(eWih0 + (size_t)tid * 16);
        float v[16];
        *(float4*)(v + 0)  = s[0];
        *(float4*)(v + 4)  = s[1];
        *(float4*)(v + 8)  = s[2];
        *(float4*)(v + 12) = s[3];
        float* d = sm + OFF_WIH0 + tid;
#pragma unroll
        for (int k = 0; k < 16; k++) d[k * WPAD] = v[k];
    }
    __syncthreads();

    const float* hb0 = sm + OFF_H0 + rowbase;
    const float* hb1 = sm + OFF_H1 + rowbase;
    const float* xb  = sm + OFF_XS + rowbase;

    // ======================= ENCODER: 100 steps =======================
#pragma unroll 1
    for (int t = 0; t < TT; t++) {
        // stage x_t : [64 rows][16] -> xs[16][68] transposed
        if (tid < BR) {
            const float4* s = (const float4*)(x + (size_t)(gr0 + tid) * (TT * INF) + t * INF);
            float v[16];
            *(float4*)(v + 0)  = s[0];
            *(float4*)(v + 4)  = s[1];
            *(float4*)(v + 8)  = s[2];
            *(float4*)(v + 12) = s[3];
            float* d = sm + OFF_XS + tid;
#pragma unroll
            for (int k = 0; k < 16; k++) d[k * HPAD] = v[k];
        }
        __syncthreads();

        // ---- layer 0 ----
        u64 acc[4][8];
        init_acc(acc, sm + OFF_BIAS, j);
        accum<16>(acc, sm + OFF_WIH0, xb, j);        // x part, K=16
        gemm128(acc, eWhh0, hb0, sm, tid, j);        // h part, K=128
        __syncthreads();                              // readers of h0 done
        epilogue(acc, sm + OFF_C0, sm + OFF_H0, j, rowbase);
        __syncthreads();                              // new h0 visible

        // ---- layer 1 ----
        init_acc(acc, sm + OFF_BIAS + 512, j);
        gemm128(acc, eWih1, hb0, sm, tid, j);        // input = h0_t
        gemm128(acc, eWhh1, hb1, sm, tid, j);        // recurrent
        __syncthreads();
        epilogue(acc, sm + OFF_C1, sm + OFF_H1, j, rowbase);
        __syncthreads();                              // protect xs rewrite next t
    }

    // ======================= DECODER setup =======================
    {   // dWih0 [512][2] -> transposed [2][516] (reuse WIH0 region)
        const float2* s = (const float2*)(dWih0 + (size_t)tid * 2);
        float2 v = s[0];
        sm[OFF_WIH0 + tid]        = v.x;
        sm[OFF_WIH0 + WPAD + tid] = v.y;
    }
    if (tid < BR) {  // dec_in = x[:, 99, :2]
        size_t base = (size_t)(gr0 + tid) * (TT * INF) + 99 * INF;
        sm[OFF_XS + tid]        = x[base + 0];
        sm[OFF_XS + HPAD + tid] = x[base + 1];
    }
    __syncthreads();

    // ======================= DECODER: 60 steps =======================
#pragma unroll 1
    for (int t = 0; t < TGTN; t++) {
        // ---- layer 0 ----
        u64 acc[4][8];
        init_acc(acc, sm + OFF_BIAS + 1024, j);
        accum<2>(acc, sm + OFF_WIH0, xb, j);         // input part, K=2
        gemm128(acc, dWhh0, hb0, sm, tid, j);
        __syncthreads();
        epilogue(acc, sm + OFF_C0, sm + OFF_H0, j, rowbase);
        __syncthreads();

        // ---- layer 1 ----
        init_acc(acc, sm + OFF_BIAS + 1536, j);
        gemm128(acc, dWih1, hb0, sm, tid, j);
        gemm128(acc, dWhh1, hb1, sm, tid, j);
        __syncthreads();
        epilogue(acc, sm + OFF_C1, sm + OFF_H1, j, rowbase);
        __syncthreads();                              // h1 ready for FC

        // ---- FC + output + feedback ----
        if (tid < 2 * BR) {
            int r = tid >> 1;
            int o = tid & 1;
            float s = sm[OFF_FCB + o];
            const float* fw = sm + OFF_FC + o * 128;
            const float* hv = sm + OFF_H1 + r;
#pragma unroll 8
            for (int jj = 0; jj < 128; jj++) s += hv[jj * HPAD] * fw[jj];
            out[((size_t)(gr0 + r) * TGTN + t) * 2 + o] = s;
            sm[OFF_XS + o * HPAD + r] = s;            // next decoder input
        }
        __syncthreads();
    }
}

extern "C" void kernel_launch(void* const* d_in, const int* in_sizes, int n_in,
                              void* d_out, int out_size)
{
    const float* x     = (const float*)d_in[0];
    // d_in[1] = target_len (fixed = 60, hardcoded)
    const float* eWih0 = (const float*)d_in[2];
    const float* eWhh0 = (const float*)d_in[3];
    const float* ebih0 = (const float*)d_in[4];
    const float* ebhh0 = (const float*)d_in[5];
    const float* eWih1 = (const float*)d_in[6];
    const float* eWhh1 = (const float*)d_in[7];
    const float* ebih1 = (const float*)d_in[8];
    const float* ebhh1 = (const float*)d_in[9];
    const float* dWih0 = (const float*)d_in[10];
    const float* dWhh0 = (const float*)d_in[11];
    const float* dbih0 = (const float*)d_in[12];
    const float* dbhh0 = (const float*)d_in[13];
    const float* dWih1 = (const float*)d_in[14];
    const float* dWhh1 = (const float*)d_in[15];
    const float* dbih1 = (const float*)d_in[16];
    const float* dbhh1 = (const float*)d_in[17];
    const float* fcW   = (const float*)d_in[18];
    const float* fcb   = (const float*)d_in[19];
    float* out = (float*)d_out;

    cudaFuncSetAttribute(lstm_traj_kernel,
                         cudaFuncAttributeMaxDynamicSharedMemorySize, SMEM_BYTES);

    lstm_traj_kernel<<<BB / BR, NT, SMEM_BYTES>>>(
        x, eWih0, eWhh0, ebih0, ebhh0, eWih1, eWhh1, ebih1, ebhh1,
        dWih0, dWhh0, dbih0, dbhh0, dWih1, dWhh1, dbih1, dbhh1,
        fcW, fcb, out);
}

// round 3
// speedup vs baseline: 1.2857x; 1.2857x over previous
#include <cuda_runtime.h>
#include <cstdint>

// Problem constants
#define BB    8192
#define TT    100
#define INF   16
#define TGTN  60

#define NT    256     // threads per CTA
#define BR    32      // batch rows per CTA
#define HPAD  36      // state row stride (floats): 16B-aligned, conflict-free
#define WPAD  516     // weight chunk gate stride (floats)
#define CHW   (8*WPAD) // one 8-k weight buffer (floats)

// Shared layout (float offsets). All 16B-aligned.
#define OFF_H0   0
#define OFF_H1   4608              // 128*36
#define OFF_C0   9216
#define OFF_C1   13824
#define OFF_WBUF 18432             // 2 x [8][516] = 8256 floats
#define OFF_XS   26688             // [16][36] = 576
#define OFF_FC   27264             // fcW [2][128]
#define OFF_FCB  27520
#define SMEM_FLOATS 27524
#define SMEM_BYTES  (SMEM_FLOATS*4)   // 110,096 B -> 2 CTAs / SM

typedef unsigned long long u64;

// ---- packed f32x2 helpers ----
__device__ __forceinline__ u64 pk2(float x) {
    u64 r; asm("mov.b64 %0, {%1, %1};" : "=l"(r) : "f"(x)); return r;
}
__device__ __forceinline__ u64 f2fma(u64 a, u64 b, u64 c) {
    u64 d; asm("fma.rn.f32x2 %0, %1, %2, %3;" : "=l"(d) : "l"(a), "l"(b), "l"(c)); return d;
}
__device__ __forceinline__ float2 up2(u64 v) {
    float2 f; asm("mov.b64 {%0, %1}, %2;" : "=f"(f.x), "=f"(f.y) : "l"(v)); return f;
}

// ---- activations ----
__device__ __forceinline__ float sigm(float x) {
    return __fdividef(1.0f, 1.0f + __expf(-x));
}
__device__ __forceinline__ float tanh_(float x) {
    float a = fabsf(x);
    float e = __expf(-2.0f * a);
    float t = __fdividef(1.0f - e, 1.0f + e);
    return copysignf(t, x);
}

// ---- inner accumulate: KS k-slices from wbuf [KS][WPAD] x act [k][HPAD] ----
template<int KS>
__device__ __forceinline__ void accumK(u64 acc[4][8],
                                       const float* __restrict__ wb,
                                       const float* __restrict__ hb,
                                       int j)
{
#pragma unroll
    for (int k = 0; k < KS; k++) {
        const float* w = wb + k * WPAD + j;
        u64 b0 = pk2(w[0]);
        u64 b1 = pk2(w[128]);
        u64 b2 = pk2(w[256]);
        u64 b3 = pk2(w[384]);
        const ulonglong2* hp = (const ulonglong2*)(hb + k * HPAD);
        ulonglong2 q0 = hp[0], q1 = hp[1], q2 = hp[2], q3 = hp[3];
        u64 a[8] = {q0.x, q0.y, q1.x, q1.y, q2.x, q2.y, q3.x, q3.y};
#pragma unroll
        for (int p = 0; p < 8; p++) {
            acc[0][p] = f2fma(a[p], b0, acc[0][p]);
            acc[1][p] = f2fma(a[p], b1, acc[1][p]);
            acc[2][p] = f2fma(a[p], b2, acc[2][p]);
            acc[3][p] = f2fma(a[p], b3, acc[3][p]);
        }
    }
}

// ---- streamed GEMM: W [512][ldw] row-major, K = NCH*8, double-buffered,
//      one barrier per chunk, LDG overlapped 2 chunks ahead ----
template<int NCH>
__device__ __forceinline__ void gemm_stream(u64 acc[4][8],
                                            const float* __restrict__ W, int ldw,
                                            const float* __restrict__ hb,
                                            float* __restrict__ sm, int tid, int j)
{
    float* wb = sm + OFF_WBUF;
    const int g0 = tid, g1 = tid + NT;
    float4 ra0, ra1, rb0, rb1;

    auto ldch = [&](int c) {
        const float4* p0 = (const float4*)(W + (size_t)g0 * ldw + c * 8);
        const float4* p1 = (const float4*)(W + (size_t)g1 * ldw + c * 8);
        ra0 = p0[0]; ra1 = p0[1];
        rb0 = p1[0]; rb1 = p1[1];
    };
    auto stch = [&](int b) {
        float* d = wb + b * CHW;
        d[0*WPAD+g0]=ra0.x; d[1*WPAD+g0]=ra0.y; d[2*WPAD+g0]=ra0.z; d[3*WPAD+g0]=ra0.w;
        d[4*WPAD+g0]=ra1.x; d[5*WPAD+g0]=ra1.y; d[6*WPAD+g0]=ra1.z; d[7*WPAD+g0]=ra1.w;
        d[0*WPAD+g1]=rb0.x; d[1*WPAD+g1]=rb0.y; d[2*WPAD+g1]=rb0.z; d[3*WPAD+g1]=rb0.w;
        d[4*WPAD+g1]=rb1.x; d[5*WPAD+g1]=rb1.y; d[6*WPAD+g1]=rb1.z; d[7*WPAD+g1]=rb1.w;
    };

    ldch(0); stch(0);
    if (NCH > 1) ldch(1);
    __syncthreads();                    // buf0 visible
#pragma unroll 1
    for (int c = 0; c < NCH; c++) {
        if (c + 1 < NCH) {
            stch((c + 1) & 1);          // safe: readers of that buf done 2 chunks ago
            if (c + 2 < NCH) ldch(c + 2);
        }
        accumK<8>(acc, wb + (c & 1) * CHW, hb + c * 8 * HPAD, j);
        __syncthreads();                // STS(c+1) visible; buf[c&1] free
    }
}

__device__ __forceinline__ void init_acc_r(u64 acc[4][8], const float b[4])
{
#pragma unroll
    for (int g = 0; g < 4; g++) {
        u64 bb = pk2(b[g]);
#pragma unroll
        for (int p = 0; p < 8; p++) acc[g][p] = bb;
    }
}

// ---- LSTM pointwise epilogue for unit j, rows rb*16..rb*16+15 ----
__device__ __forceinline__ void epilogue(u64 acc[4][8],
                                         float* __restrict__ cs,
                                         float* __restrict__ hs,
                                         int j, int rb)
{
    float2* cp = (float2*)(cs + j * HPAD + rb * 16);
    float2* hp = (float2*)(hs + j * HPAD + rb * 16);
#pragma unroll
    for (int p = 0; p < 8; p++) {
        float2 gi = up2(acc[0][p]);
        float2 gf = up2(acc[1][p]);
        float2 gg = up2(acc[2][p]);
        float2 go = up2(acc[3][p]);
        float2 c = cp[p];
        float cn0 = sigm(gf.x) * c.x + sigm(gi.x) * tanh_(gg.x);
        float cn1 = sigm(gf.y) * c.y + sigm(gi.y) * tanh_(gg.y);
        cp[p] = make_float2(cn0, cn1);
        hp[p] = make_float2(sigm(go.x) * tanh_(cn0), sigm(go.y) * tanh_(cn1));
    }
}

__global__ void __launch_bounds__(NT, 2)
lstm_traj_kernel(const float* __restrict__ x,
                 const float* __restrict__ eWih0, const float* __restrict__ eWhh0,
                 const float* __restrict__ ebih0, const float* __restrict__ ebhh0,
                 const float* __restrict__ eWih1, const float* __restrict__ eWhh1,
                 const float* __restrict__ ebih1, const float* __restrict__ ebhh1,
                 const float* __restrict__ dWih0, const float* __restrict__ dWhh0,
                 const float* __restrict__ dbih0, const float* __restrict__ dbhh0,
                 const float* __restrict__ dWih1, const float* __restrict__ dWhh1,
                 const float* __restrict__ dbih1, const float* __restrict__ dbhh1,
                 const float* __restrict__ fcW,  const float* __restrict__ fcb,
                 float* __restrict__ out)
{
    extern __shared__ float sm[];
    const int tid = threadIdx.x;
    const int j  = tid >> 1;            // hidden unit 0..127
    const int rb = tid & 1;             // row block: rows rb*16..rb*16+15
    const int gr0 = blockIdx.x * BR;

    // biases, combined, in registers
    float be0[4], be1[4], bd0[4], bd1[4];
#pragma unroll
    for (int g = 0; g < 4; g++) {
        int idx = g * 128 + j;
        be0[g] = ebih0[idx] + ebhh0[idx];
        be1[g] = ebih1[idx] + ebhh1[idx];
        bd0[g] = dbih0[idx] + dbhh0[idx];
        bd1[g] = dbih1[idx] + dbhh1[idx];
    }

    // zero states; stage FC weights
    for (int i = tid; i < 4 * 128 * HPAD; i += NT) sm[i] = 0.0f;
    sm[OFF_FC + tid] = fcW[tid & 255];        // 256 valid entries
    if (tid < 2) sm[OFF_FCB + tid] = fcb[tid];
    __syncthreads();

    const float* hb0 = sm + OFF_H0 + rb * 16;
    const float* hb1 = sm + OFF_H1 + rb * 16;
    const float* xb  = sm + OFF_XS + rb * 16;

    // ======================= ENCODER =======================
#pragma unroll 1
    for (int t = 0; t < TT; t++) {
        if (tid < BR) {       // stage x_t transposed: xs[k][row]
            const float4* s = (const float4*)(x + (size_t)(gr0 + tid) * (TT * INF) + t * INF);
            float v[16];
            *(float4*)(v + 0)  = s[0];
            *(float4*)(v + 4)  = s[1];
            *(float4*)(v + 8)  = s[2];
            *(float4*)(v + 12) = s[3];
            float* d = sm + OFF_XS + tid;
#pragma unroll
            for (int k = 0; k < 16; k++) d[k * HPAD] = v[k];
        }
        __syncthreads();

        u64 acc[4][8];
        // layer 0
        init_acc_r(acc, be0);
        gemm_stream<2>(acc, eWih0, 16, xb, sm, tid, j);
        gemm_stream<16>(acc, eWhh0, 128, hb0, sm, tid, j);
        epilogue(acc, sm + OFF_C0, sm + OFF_H0, j, rb);
        __syncthreads();
        // layer 1
        init_acc_r(acc, be1);
        gemm_stream<16>(acc, eWih1, 128, hb0, sm, tid, j);
        gemm_stream<16>(acc, eWhh1, 128, hb1, sm, tid, j);
        epilogue(acc, sm + OFF_C1, sm + OFF_H1, j, rb);
        __syncthreads();
    }

    // ======================= DECODER setup =======================
    if (tid < BR) {
        size_t base = (size_t)(gr0 + tid) * (TT * INF) + 99 * INF;
        sm[OFF_XS + tid]        = x[base + 0];
        sm[OFF_XS + HPAD + tid] = x[base + 1];
    }
    __syncthreads();

    // ======================= DECODER =======================
#pragma unroll 1
    for (int t = 0; t < TGTN; t++) {
        u64 acc[4][8];
        // layer 0: K=2 input part + K=128 recurrent
        init_acc_r(acc, bd0);
        {   // mini-chunk: dWih0 [512][2] -> wbuf[2][516]
            float* wb = sm + OFF_WBUF;
            float2 w0 = *(const float2*)(dWih0 + tid * 2);
            float2 w1 = *(const float2*)(dWih0 + (tid + NT) * 2);
            wb[tid]             = w0.x;
            wb[WPAD + tid]      = w0.y;
            wb[tid + NT]        = w1.x;
            wb[WPAD + tid + NT] = w1.y;
            __syncthreads();
            accumK<2>(acc, wb, xb, j);
            __syncthreads();
        }
        gemm_stream<16>(acc, dWhh0, 128, hb0, sm, tid, j);
        epilogue(acc, sm + OFF_C0, sm + OFF_H0, j, rb);
        __syncthreads();
        // layer 1
        init_acc_r(acc, bd1);
        gemm_stream<16>(acc, dWih1, 128, hb0, sm, tid, j);
        gemm_stream<16>(acc, dWhh1, 128, hb1, sm, tid, j);
        epilogue(acc, sm + OFF_C1, sm + OFF_H1, j, rb);
        __syncthreads();

        // FC + output + feedback
        if (tid < 2 * BR) {
            int r = tid >> 1;
            int o = tid & 1;
            float s = sm[OFF_FCB + o];
            const float* fw = sm + OFF_FC + o * 128;
            const float* hv = sm + OFF_H1 + r;
#pragma unroll 8
            for (int jj = 0; jj < 128; jj++) s += hv[jj * HPAD] * fw[jj];
            out[((size_t)(gr0 + r) * TGTN + t) * 2 + o] = s;
            sm[OFF_XS + o * HPAD + r] = s;
        }
        __syncthreads();
    }
}

extern "C" void kernel_launch(void* const* d_in, const int* in_sizes, int n_in,
                              void* d_out, int out_size)
{
    const float* x     = (const float*)d_in[0];
    const float* eWih0 = (const float*)d_in[2];
    const float* eWhh0 = (const float*)d_in[3];
    const float* ebih0 = (const float*)d_in[4];
    const float* ebhh0 = (const float*)d_in[5];
    const float* eWih1 = (const float*)d_in[6];
    const float* eWhh1 = (const float*)d_in[7];
    const float* ebih1 = (const float*)d_in[8];
    const float* ebhh1 = (const float*)d_in[9];
    const float* dWih0 = (const float*)d_in[10];
    const float* dWhh0 = (const float*)d_in[11];
    const float* dbih0 = (const float*)d_in[12];
    const float* dbhh0 = (const float*)d_in[13];
    const float* dWih1 = (const float*)d_in[14];
    const float* dWhh1 = (const float*)d_in[15];
    const float* dbih1 = (const float*)d_in[16];
    const float* dbhh1 = (const float*)d_in[17];
    const float* fcW   = (const float*)d_in[18];
    const float* fcb   = (const float*)d_in[19];
    float* out = (float*)d_out;

    cudaFuncSetAttribute(lstm_traj_kernel,
                         cudaFuncAttributeMaxDynamicSharedMemorySize, SMEM_BYTES);

    lstm_traj_kernel<<<BB / BR, NT, SMEM_BYTES>>>(
        x, eWih0, eWhh0, ebih0, ebhh0, eWih1, eWhh1, ebih1, ebhh1,
        dWih0, dWhh0, dbih0, dbhh0, dWih1, dWhh1, dbih1, dbhh1,
        fcW, fcb, out);
}